// round 5
// baseline (speedup 1.0000x reference)
#include <cuda_runtime.h>

// WeatherDifferentiatedAttention — fused, one CTA per (b,t) sequence.
// Round 4: f32x2 packed FMA (FFMA2) in all broadcast-GEMM loops + 8-row
// register tiles in stage 1. Lane = (h, et) as before.

constexpr int NTHR = 512;
constexpr int NWARP = 16;
constexpr int NT = 200, NW = 100, CM = 256;

// smem float offsets
constexpr int OFF_X = 0;                   // [200][64]  x / q / o
constexpr int OFF_K = 12800;               // [208][68]  h_w / k  (stage5: opT)
constexpr int OFF_V = OFF_K + 208 * 68;    // [208][68]  h_t / v
constexpr int OFF_W = OFF_V + 208 * 68;    // 13312: weights / probs / A-buf
constexpr int SMEM_F = OFF_W + 13312;      // 54400 floats = 217600 B

typedef unsigned long long u64;

__device__ __forceinline__ float4 ld4(const float* p) {
    return *reinterpret_cast<const float4*>(p);
}
__device__ __forceinline__ void st4(float* p, const float4 v) {
    *reinterpret_cast<float4*>(p) = v;
}
__device__ __forceinline__ ulonglong2 ld4u(const float* p) {
    return *reinterpret_cast<const ulonglong2*>(p);
}
__device__ __forceinline__ void st4u(float* p, const u64 lo, const u64 hi) {
    *reinterpret_cast<ulonglong2*>(p) = make_ulonglong2(lo, hi);
}
// pack scalar into both f32x2 lanes
__device__ __forceinline__ u64 pk1(float s) {
    u64 r; unsigned u = __float_as_uint(s);
    asm("mov.b64 %0, {%1, %1};" : "=l"(r) : "r"(u));
    return r;
}
__device__ __forceinline__ u64 pk2(float lo, float hi) {
    u64 r;
    asm("mov.b64 %0, {%1, %2};" : "=l"(r)
        : "r"(__float_as_uint(lo)), "r"(__float_as_uint(hi)));
    return r;
}
__device__ __forceinline__ void upk(u64 v, float& lo, float& hi) {
    unsigned a, b;
    asm("mov.b64 {%0, %1}, %2;" : "=r"(a), "=r"(b) : "l"(v));
    lo = __uint_as_float(a); hi = __uint_as_float(b);
}
// acc (f32x2) += s2 * wv  (elementwise packed fp32 FMA)
#define FMA2(acc, s2, wv) \
    asm("fma.rn.f32x2 %0, %1, %2, %0;" : "+l"(acc) : "l"(s2), "l"(wv))
#define FMA4P(a0, a1, s2, wv) { u64 _s = (s2); FMA2(a0, _s, (wv).x); FMA2(a1, _s, (wv).y); }

__device__ __forceinline__ float hsum16(float v) {
    v += __shfl_xor_sync(0xffffffffu, v, 1);
    v += __shfl_xor_sync(0xffffffffu, v, 2);
    v += __shfl_xor_sync(0xffffffffu, v, 4);
    v += __shfl_xor_sync(0xffffffffu, v, 8);
    return v;
}
__device__ __forceinline__ float hmax16(float v) {
    v = fmaxf(v, __shfl_xor_sync(0xffffffffu, v, 1));
    v = fmaxf(v, __shfl_xor_sync(0xffffffffu, v, 2));
    v = fmaxf(v, __shfl_xor_sync(0xffffffffu, v, 4));
    v = fmaxf(v, __shfl_xor_sync(0xffffffffu, v, 8));
    return v;
}
__device__ __forceinline__ float dot4(const float4 a, const float4 b, float acc) {
    return fmaf(a.x, b.x, fmaf(a.y, b.y, fmaf(a.z, b.z, fmaf(a.w, b.w, acc))));
}

__global__ __launch_bounds__(NTHR, 1) void wda_kernel(
    const float* __restrict__ turb, const float* __restrict__ weath,
    const float* __restrict__ w_t,  const float* __restrict__ b_t,
    const float* __restrict__ w_w,  const float* __restrict__ b_w,
    const float* __restrict__ g_t,  const float* __restrict__ be_t,
    const float* __restrict__ g_w,  const float* __restrict__ be_w,
    const float* __restrict__ w_qkv,const float* __restrict__ b_qkv,
    const float* __restrict__ w_ao, const float* __restrict__ b_ao,
    const float* __restrict__ w_op, const float* __restrict__ b_op,
    float* __restrict__ out)
{
    extern __shared__ float sm[];
    const int tid  = threadIdx.x;
    const int warp = tid >> 5, lane = tid & 31;
    const int hh   = lane >> 4;           // half-warp id
    const int hh2  = hh * 2;
    const int et   = lane & 15;
    const int e4   = et * 4;
    const size_t s = blockIdx.x;
    const float* turb_s  = turb  + s * (size_t)(NT * CM);
    const float* weath_s = weath + s * (size_t)(NW * CM);
    float*       out_s   = out   + s * (size_t)(NT * CM);

    // zero V pad rows 200..207 (stage-4 context over-reads with p=0)
    for (int i = tid; i < 8 * 68; i += NTHR) sm[OFF_V + 200 * 68 + i] = 0.f;

    // ============ Stage 1: h = LN(x @ W^T + b), 8-row tiles per warp ======
#pragma unroll 1
    for (int src = 0; src < 2; ++src) {
        const float* inp = src ? weath_s : turb_s;
        const float* Wg  = src ? w_w  : w_t;
        const float* bg  = src ? b_w  : b_t;
        const float* gg  = src ? g_w  : g_t;
        const float* beg = src ? be_w : be_t;
        const int ngrp   = src ? 13 : 25;         // 8-row groups (weather padded)
        const int rmax   = src ? NW - 1 : NT - 1;
        float* hb = sm + (src ? OFF_K : OFF_V);
        const float4 bv = ld4(bg + e4), gv = ld4(gg + e4), ev = ld4(beg + e4);

#pragma unroll 1
        for (int ch = 0; ch < 2; ++ch) {
            __syncthreads();
            // stage wT chunk [128][68]: sm[c*68+d] = Wg[d*256 + ch*128 + c]
            for (int idx = tid; idx < 64 * 128; idx += NTHR) {
                const int d = idx >> 7, c = idx & 127;
                sm[OFF_W + c * 68 + d] = Wg[d * 256 + ch * 128 + c];
            }
            __syncthreads();
#pragma unroll 1
            for (int g = warp; g < ngrp; g += NWARP) {
                const int r0 = g * 8 + hh * 4;
                const float* xp0 = inp + (size_t)min(r0 + 0, rmax) * CM + ch * 128;
                const float* xp1 = inp + (size_t)min(r0 + 1, rmax) * CM + ch * 128;
                const float* xp2 = inp + (size_t)min(r0 + 2, rmax) * CM + ch * 128;
                const float* xp3 = inp + (size_t)min(r0 + 3, rmax) * CM + ch * 128;
                u64 ac[4][2] = {{0,0},{0,0},{0,0},{0,0}};
#pragma unroll 2
                for (int k = 0; k < 128; k += 4) {
                    const float4 x0 = ld4(xp0 + k), x1 = ld4(xp1 + k);
                    const float4 x2 = ld4(xp2 + k), x3 = ld4(xp3 + k);
                    const float* wp = sm + OFF_W + k * 68 + e4;
                    const ulonglong2 w0 = ld4u(wp),       w1 = ld4u(wp + 68),
                                     w2 = ld4u(wp + 136), w3 = ld4u(wp + 204);
                    FMA4P(ac[0][0], ac[0][1], pk1(x0.x), w0);
                    FMA4P(ac[0][0], ac[0][1], pk1(x0.y), w1);
                    FMA4P(ac[0][0], ac[0][1], pk1(x0.z), w2);
                    FMA4P(ac[0][0], ac[0][1], pk1(x0.w), w3);
                    FMA4P(ac[1][0], ac[1][1], pk1(x1.x), w0);
                    FMA4P(ac[1][0], ac[1][1], pk1(x1.y), w1);
                    FMA4P(ac[1][0], ac[1][1], pk1(x1.z), w2);
                    FMA4P(ac[1][0], ac[1][1], pk1(x1.w), w3);
                    FMA4P(ac[2][0], ac[2][1], pk1(x2.x), w0);
                    FMA4P(ac[2][0], ac[2][1], pk1(x2.y), w1);
                    FMA4P(ac[2][0], ac[2][1], pk1(x2.z), w2);
                    FMA4P(ac[2][0], ac[2][1], pk1(x2.w), w3);
                    FMA4P(ac[3][0], ac[3][1], pk1(x3.x), w0);
                    FMA4P(ac[3][0], ac[3][1], pk1(x3.y), w1);
                    FMA4P(ac[3][0], ac[3][1], pk1(x3.z), w2);
                    FMA4P(ac[3][0], ac[3][1], pk1(x3.w), w3);
                }
                if (ch == 0) {
#pragma unroll
                    for (int i = 0; i < 4; ++i)
                        st4u(hb + (r0 + i) * 68 + e4, ac[i][0], ac[i][1]);
                } else {
#pragma unroll
                    for (int i = 0; i < 4; ++i) {
                        float f0, f1, f2, f3;
                        upk(ac[i][0], f0, f1); upk(ac[i][1], f2, f3);
                        float* hr = hb + (r0 + i) * 68 + e4;
                        const float4 pv = ld4(hr);
                        float y0 = f0 + pv.x + bv.x, y1 = f1 + pv.y + bv.y;
                        float y2 = f2 + pv.z + bv.z, y3 = f3 + pv.w + bv.w;
                        const float mu = hsum16(y0 + y1 + y2 + y3) * 0.015625f;
                        const float qq = hsum16(y0*y0 + y1*y1 + y2*y2 + y3*y3) * 0.015625f;
                        const float rs = rsqrtf(qq - mu * mu + 1e-5f);
                        y0 = (y0 - mu) * rs * gv.x + ev.x;
                        y1 = (y1 - mu) * rs * gv.y + ev.y;
                        y2 = (y2 - mu) * rs * gv.z + ev.z;
                        y3 = (y3 - mu) * rs * gv.w + ev.w;
                        st4(hr, make_float4(y0, y1, y2, y3));
                    }
                }
            }
        }
    }
    __syncthreads();

    // ============ Stage 2: cross-attention, x = softmax(h_t h_w^T/8) h_w ==
    {
        float* P  = sm + OFF_W + warp * 832;
        float* pA = P + hh2 * 112;
        float* pB = pA + 112;
#pragma unroll 1
        for (int g = warp; g < NT / 4; g += NWARP) {
            const int rA = g * 4 + hh2;
            const float* qA = sm + OFF_V + rA * 68;
            const float* qB = qA + 68;
            float lA[7], lB[7];
#pragma unroll
            for (int j = 0; j < 7; ++j) { lA[j] = 0.f; lB[j] = 0.f; }
#pragma unroll
            for (int d = 0; d < 64; d += 4) {
                const float4 a = ld4(qA + d), b = ld4(qB + d);
#pragma unroll
                for (int j = 0; j < 7; ++j) {
                    const float4 kv = ld4(sm + OFF_K + (et + 16*j) * 68 + d);
                    lA[j] = dot4(a, kv, lA[j]);
                    lB[j] = dot4(b, kv, lB[j]);
                }
            }
            float mA = -1e30f, mB = -1e30f;
#pragma unroll
            for (int j = 0; j < 7; ++j) {
                const bool ok = et + 16*j < NW;
                lA[j] = ok ? lA[j] * 0.125f : -1e30f;
                lB[j] = ok ? lB[j] * 0.125f : -1e30f;
                mA = fmaxf(mA, lA[j]); mB = fmaxf(mB, lB[j]);
            }
            mA = hmax16(mA); mB = hmax16(mB);
            float sA = 0.f, sB = 0.f;
#pragma unroll
            for (int j = 0; j < 7; ++j) {
                const bool ok = et + 16*j < NW;
                lA[j] = ok ? __expf(lA[j] - mA) : 0.f;
                lB[j] = ok ? __expf(lB[j] - mB) : 0.f;
                sA += lA[j]; sB += lB[j];
            }
            const float iA = 1.f / hsum16(sA), iB = 1.f / hsum16(sB);
#pragma unroll
            for (int j = 0; j < 7; ++j) {
                const int m = et + 16*j;
                if (m < NW) { pA[m] = lA[j] * iA; pB[m] = lB[j] * iB; }
            }
            __syncwarp();
            u64 c0A = 0, c1A = 0, c0B = 0, c1B = 0;
#pragma unroll 5
            for (int m = 0; m < NW; m += 4) {
                const float4 pa = ld4(pA + m), pb = ld4(pB + m);
                const float* kp = sm + OFF_K + m * 68 + e4;
                const ulonglong2 k0 = ld4u(kp),       k1 = ld4u(kp + 68),
                                 k2 = ld4u(kp + 136), k3 = ld4u(kp + 204);
                FMA4P(c0A, c1A, pk1(pa.x), k0); FMA4P(c0A, c1A, pk1(pa.y), k1);
                FMA4P(c0A, c1A, pk1(pa.z), k2); FMA4P(c0A, c1A, pk1(pa.w), k3);
                FMA4P(c0B, c1B, pk1(pb.x), k0); FMA4P(c0B, c1B, pk1(pb.y), k1);
                FMA4P(c0B, c1B, pk1(pb.z), k2); FMA4P(c0B, c1B, pk1(pb.w), k3);
            }
            st4u(sm + OFF_X + rA * 64 + e4, c0A, c1A);
            st4u(sm + OFF_X + (rA+1) * 64 + e4, c0B, c1B);
            __syncwarp();
        }
    }
    __syncthreads();

    // ============ Stage 3: QKV projection ==================================
    for (int idx = tid; idx < 192 * 64; idx += NTHR) {
        const int e = idx >> 6, d = idx & 63;
        sm[OFF_W + d * 196 + e] = w_qkv[idx];     // wT[d][e], stride 196
    }
    __syncthreads();
    {
        const float4 bq0 = ld4(b_qkv + e4), bq1 = ld4(b_qkv + 64 + e4),
                     bq2 = ld4(b_qkv + 128 + e4);
#pragma unroll 1
        for (int g = warp; g < NT / 4; g += NWARP) {
            const int rA = g * 4 + hh2;
            const float* xA = sm + OFF_X + rA * 64;
            const float* xB = xA + 64;
            u64 q0A = pk2(bq0.x, bq0.y), q1A = pk2(bq0.z, bq0.w);
            u64 k0A = pk2(bq1.x, bq1.y), k1A = pk2(bq1.z, bq1.w);
            u64 v0A = pk2(bq2.x, bq2.y), v1A = pk2(bq2.z, bq2.w);
            u64 q0B = q0A, q1B = q1A, k0B = k0A, k1B = k1A, v0B = v0A, v1B = v1A;
#pragma unroll 4
            for (int d = 0; d < 64; d += 4) {
                const float4 a = ld4(xA + d), b = ld4(xB + d);
#define QKV_STEP(xa, xb, dd) { \
                const float* wp = sm + OFF_W + (d + dd) * 196 + e4; \
                const ulonglong2 w0 = ld4u(wp), w1 = ld4u(wp + 64), w2 = ld4u(wp + 128); \
                const u64 sa = pk1(xa), sb = pk1(xb); \
                FMA4P(q0A, q1A, sa, w0); FMA4P(k0A, k1A, sa, w1); FMA4P(v0A, v1A, sa, w2); \
                FMA4P(q0B, q1B, sb, w0); FMA4P(k0B, k1B, sb, w1); FMA4P(v0B, v1B, sb, w2); }
                QKV_STEP(a.x, b.x, 0) QKV_STEP(a.y, b.y, 1)
                QKV_STEP(a.z, b.z, 2) QKV_STEP(a.w, b.w, 3)
#undef QKV_STEP
            }
            st4u(sm + OFF_X + rA * 64 + e4, q0A, q1A);      // q overwrites x
            st4u(sm + OFF_X + (rA+1) * 64 + e4, q0B, q1B);
            st4u(sm + OFF_K + rA * 68 + e4, k0A, k1A);
            st4u(sm + OFF_K + (rA+1) * 68 + e4, k0B, k1B);
            st4u(sm + OFF_V + rA * 68 + e4, v0A, v1A);
            st4u(sm + OFF_V + (rA+1) * 68 + e4, v0B, v1B);
        }
    }
    __syncthreads();

    // ============ Stage 4: 4-head self-attention (o overwrites q) ==========
    {
        float* P  = sm + OFF_W + warp * 832;          // [4][208]
        float* pA = P + hh2 * 208;
        float* pB = pA + 208;
        const int ms = et >> 2, dd4 = (et & 3) * 4;
#pragma unroll 1
        for (int g = warp; g < NT / 4; g += NWARP) {
            const int rA = g * 4 + hh2;
            if (et < 8) { pA[200 + et] = 0.f; pB[200 + et] = 0.f; }
#pragma unroll 1
            for (int hd0 = 0; hd0 < 64; hd0 += 16) {
                const float* qA = sm + OFF_X + rA * 64 + hd0;
                const float* qB = qA + 64;
                float lA[13], lB[13];
#pragma unroll
                for (int j = 0; j < 13; ++j) { lA[j] = 0.f; lB[j] = 0.f; }
#pragma unroll
                for (int d = 0; d < 16; d += 4) {
                    const float4 a = ld4(qA + d), b = ld4(qB + d);
#pragma unroll
                    for (int j = 0; j < 13; ++j) {
                        const float4 kv = ld4(sm + OFF_K + (et + 16*j) * 68 + hd0 + d);
                        lA[j] = dot4(a, kv, lA[j]);
                        lB[j] = dot4(b, kv, lB[j]);
                    }
                }
                float mA = -1e30f, mB = -1e30f;
#pragma unroll
                for (int j = 0; j < 13; ++j) {
                    const bool ok = et + 16*j < NT;
                    lA[j] = ok ? lA[j] * 0.25f : -1e30f;
                    lB[j] = ok ? lB[j] * 0.25f : -1e30f;
                    mA = fmaxf(mA, lA[j]); mB = fmaxf(mB, lB[j]);
                }
                mA = hmax16(mA); mB = hmax16(mB);
                float sA = 0.f, sB = 0.f;
#pragma unroll
                for (int j = 0; j < 13; ++j) {
                    const bool ok = et + 16*j < NT;
                    lA[j] = ok ? __expf(lA[j] - mA) : 0.f;
                    lB[j] = ok ? __expf(lB[j] - mB) : 0.f;
                    sA += lA[j]; sB += lB[j];
                }
                const float iA = 1.f / hsum16(sA), iB = 1.f / hsum16(sB);
#pragma unroll
                for (int j = 0; j < 13; ++j) {
                    const int m = et + 16*j;
                    if (m < NT) { pA[m] = lA[j] * iA; pB[m] = lB[j] * iB; }
                }
                __syncwarp();
                u64 o0A = 0, o1A = 0, o0B = 0, o1B = 0;
                const int m0 = ms * 52;
#pragma unroll
                for (int mi = 0; mi < 52; mi += 4) {
                    const int m = m0 + mi;
                    const float4 pa = ld4(pA + m), pb = ld4(pB + m);
                    const float* vp = sm + OFF_V + m * 68 + hd0 + dd4;
                    const ulonglong2 v0 = ld4u(vp),       v1 = ld4u(vp + 68),
                                     v2 = ld4u(vp + 136), v3 = ld4u(vp + 204);
                    FMA4P(o0A, o1A, pk1(pa.x), v0); FMA4P(o0A, o1A, pk1(pa.y), v1);
                    FMA4P(o0A, o1A, pk1(pa.z), v2); FMA4P(o0A, o1A, pk1(pa.w), v3);
                    FMA4P(o0B, o1B, pk1(pb.x), v0); FMA4P(o0B, o1B, pk1(pb.y), v1);
                    FMA4P(o0B, o1B, pk1(pb.z), v2); FMA4P(o0B, o1B, pk1(pb.w), v3);
                }
                float4 oA, oB;
                upk(o0A, oA.x, oA.y); upk(o1A, oA.z, oA.w);
                upk(o0B, oB.x, oB.y); upk(o1B, oB.z, oB.w);
#define RED48(c) { c += __shfl_xor_sync(0xffffffffu, c, 4); \
                   c += __shfl_xor_sync(0xffffffffu, c, 8); }
                RED48(oA.x) RED48(oA.y) RED48(oA.z) RED48(oA.w)
                RED48(oB.x) RED48(oB.y) RED48(oB.z) RED48(oB.w)
#undef RED48
                if (ms == 0) {
                    st4(sm + OFF_X + rA * 64 + hd0 + dd4, oA);
                    st4(sm + OFF_X + (rA+1) * 64 + hd0 + dd4, oB);
                }
                __syncwarp();
            }
        }
    }
    __syncthreads();

    // ============ Stage 5: attn_out -> out_proj + residual =================
    for (int idx = tid; idx < 64 * 64; idx += NTHR) {
        const int e = idx >> 6, d = idx & 63;
        sm[OFF_W + d * 68 + e] = w_ao[idx];           // aoT[d][e], stride 68
    }
    for (int idx = tid; idx < 256 * 64; idx += NTHR) {
        const int c = idx >> 6, e = idx & 63;
        sm[OFF_K + e * 260 + c] = w_op[idx];          // opT[e][c], stride 260
    }
    __syncthreads();
    {
        const float4 bao  = ld4(b_ao + e4);
        const float4 bop0 = ld4(b_op + e4),       bop1 = ld4(b_op + 64 + e4),
                     bop2 = ld4(b_op + 128 + e4), bop3 = ld4(b_op + 192 + e4);
        float* Abuf = sm + OFF_W + 4352 + warp * 288;
#pragma unroll 1
        for (int g = warp; g < NT / 4; g += NWARP) {
            const int rA = g * 4 + hh2;
            const float* oA = sm + OFF_X + rA * 64;
            const float* oB = oA + 64;
            u64 a0A = pk2(bao.x, bao.y), a1A = pk2(bao.z, bao.w);
            u64 a0B = a0A, a1B = a1A;
#pragma unroll 4
            for (int d = 0; d < 64; d += 4) {
                const float4 a = ld4(oA + d), b = ld4(oB + d);
                const float* wp = sm + OFF_W + d * 68 + e4;
                const ulonglong2 w0 = ld4u(wp),       w1 = ld4u(wp + 68),
                                 w2 = ld4u(wp + 136), w3 = ld4u(wp + 204);
                FMA4P(a0A, a1A, pk1(a.x), w0); FMA4P(a0A, a1A, pk1(a.y), w1);
                FMA4P(a0A, a1A, pk1(a.z), w2); FMA4P(a0A, a1A, pk1(a.w), w3);
                FMA4P(a0B, a1B, pk1(b.x), w0); FMA4P(a0B, a1B, pk1(b.y), w1);
                FMA4P(a0B, a1B, pk1(b.z), w2); FMA4P(a0B, a1B, pk1(b.w), w3);
            }
            st4u(Abuf + hh2 * 68 + e4, a0A, a1A);
            st4u(Abuf + hh2 * 68 + 68 + e4, a0B, a1B);
            __syncwarp();
            const float* tA = turb_s + (size_t)rA * CM;
            const float* tB = tA + CM;
            float* outA = out_s + (size_t)rA * CM;
            float* outB = outA + CM;
            u64 aA[8], aB[8];
            {
                float4 r;
                r = ld4(tA + e4);
                aA[0] = pk2(bop0.x + r.x, bop0.y + r.y); aA[1] = pk2(bop0.z + r.z, bop0.w + r.w);
                r = ld4(tA + 64 + e4);
                aA[2] = pk2(bop1.x + r.x, bop1.y + r.y); aA[3] = pk2(bop1.z + r.z, bop1.w + r.w);
                r = ld4(tA + 128 + e4);
                aA[4] = pk2(bop2.x + r.x, bop2.y + r.y); aA[5] = pk2(bop2.z + r.z, bop2.w + r.w);
                r = ld4(tA + 192 + e4);
                aA[6] = pk2(bop3.x + r.x, bop3.y + r.y); aA[7] = pk2(bop3.z + r.z, bop3.w + r.w);
                r = ld4(tB + e4);
                aB[0] = pk2(bop0.x + r.x, bop0.y + r.y); aB[1] = pk2(bop0.z + r.z, bop0.w + r.w);
                r = ld4(tB + 64 + e4);
                aB[2] = pk2(bop1.x + r.x, bop1.y + r.y); aB[3] = pk2(bop1.z + r.z, bop1.w + r.w);
                r = ld4(tB + 128 + e4);
                aB[4] = pk2(bop2.x + r.x, bop2.y + r.y); aB[5] = pk2(bop2.z + r.z, bop2.w + r.w);
                r = ld4(tB + 192 + e4);
                aB[6] = pk2(bop3.x + r.x, bop3.y + r.y); aB[7] = pk2(bop3.z + r.z, bop3.w + r.w);
            }
            const float* arowA = Abuf + hh2 * 68;
            const float* arowB = arowA + 68;
#pragma unroll 2
            for (int e = 0; e < 64; e += 4) {
                const float4 a = ld4(arowA + e), b = ld4(arowB + e);
#define OP_STEP(xa, xb, ee) { \
                const float* wp = sm + OFF_K + (e + ee) * 260 + e4; \
                const ulonglong2 w0 = ld4u(wp),       w1 = ld4u(wp + 64), \
                                 w2 = ld4u(wp + 128), w3 = ld4u(wp + 192); \
                const u64 sa = pk1(xa), sb = pk1(xb); \
                FMA4P(aA[0], aA[1], sa, w0); FMA4P(aA[2], aA[3], sa, w1); \
                FMA4P(aA[4], aA[5], sa, w2); FMA4P(aA[6], aA[7], sa, w3); \
                FMA4P(aB[0], aB[1], sb, w0); FMA4P(aB[2], aB[3], sb, w1); \
                FMA4P(aB[4], aB[5], sb, w2); FMA4P(aB[6], aB[7], sb, w3); }
                OP_STEP(a.x, b.x, 0) OP_STEP(a.y, b.y, 1)
                OP_STEP(a.z, b.z, 2) OP_STEP(a.w, b.w, 3)
#undef OP_STEP
            }
            st4u(outA + e4,       aA[0], aA[1]); st4u(outA + 64 + e4,  aA[2], aA[3]);
            st4u(outA + 128 + e4, aA[4], aA[5]); st4u(outA + 192 + e4, aA[6], aA[7]);
            st4u(outB + e4,       aB[0], aB[1]); st4u(outB + 64 + e4,  aB[2], aB[3]);
            st4u(outB + 128 + e4, aB[4], aB[5]); st4u(outB + 192 + e4, aB[6], aB[7]);
            __syncwarp();
        }
    }
}

extern "C" void kernel_launch(void* const* d_in, const int* in_sizes, int n_in,
                              void* d_out, int out_size)
{
    const float* turb  = (const float*)d_in[0];
    const float* weath = (const float*)d_in[1];
    const float* w_t   = (const float*)d_in[2];
    const float* b_t   = (const float*)d_in[3];
    const float* w_w   = (const float*)d_in[4];
    const float* b_w   = (const float*)d_in[5];
    const float* g_t   = (const float*)d_in[6];
    const float* be_t  = (const float*)d_in[7];
    const float* g_w   = (const float*)d_in[8];
    const float* be_w  = (const float*)d_in[9];
    const float* w_qkv = (const float*)d_in[10];
    const float* b_qkv = (const float*)d_in[11];
    const float* w_ao  = (const float*)d_in[12];
    const float* b_ao  = (const float*)d_in[13];
    const float* w_op  = (const float*)d_in[14];
    const float* b_op  = (const float*)d_in[15];
    float* out = (float*)d_out;

    const int S = in_sizes[0] / (NT * CM);   // 768
    const size_t smem = (size_t)SMEM_F * sizeof(float);
    cudaFuncSetAttribute(wda_kernel, cudaFuncAttributeMaxDynamicSharedMemorySize,
                         (int)smem);
    wda_kernel<<<S, NTHR, smem>>>(turb, weath, w_t, b_t, w_w, b_w,
                                  g_t, be_t, g_w, be_w, w_qkv, b_qkv,
                                  w_ao, b_ao, w_op, b_op, out);
}

// round 6
// speedup vs baseline: 1.1666x; 1.1666x over previous
#include <cuda_runtime.h>

// WeatherDifferentiatedAttention — fused, one CTA per (b,t) sequence.
// Round 6: bf16x2 smem storage for lane-varying streams (weights, h, K, V),
// fp32 math via f32x2 FMA; unpack = shift/mask on ALU pipe.

constexpr int NTHR = 512;
constexpr int NWARP = 16;
constexpr int NT = 200, NW = 100, CM = 256;

// regions: OFF_X fp32 [200][64]; KU/VU bf16x2 [208][34 u32]; WU weights bf16x2;
// PF fp32 probs (16 warps x 832) also hosts stage-5 Abuf.
constexpr int OFF_X = 0;
constexpr int KU = 12800;
constexpr int VU = KU + 208 * 34;          // 19872
constexpr int WU = VU + 208 * 34;          // 26944 ; size 10496 u32
constexpr int OPU = WU + 2176;             // stage-5 out_proj weights
constexpr int PF = WU + 10496;             // 37440
constexpr int SMEM_F = PF + 16 * 832;      // 50752 floats = 203008 B

typedef unsigned long long u64;
typedef unsigned u32t;

__device__ __forceinline__ float4 ld4(const float* p) {
    return *reinterpret_cast<const float4*>(p);
}
__device__ __forceinline__ void st4(float* p, const float4 v) {
    *reinterpret_cast<float4*>(p) = v;
}
__device__ __forceinline__ void st4u(float* p, const u64 lo, const u64 hi) {
    *reinterpret_cast<ulonglong2*>(p) = make_ulonglong2(lo, hi);
}
__device__ __forceinline__ uint2 ld2u(const u32t* p) {
    return *reinterpret_cast<const uint2*>(p);
}
__device__ __forceinline__ void st2u(u32t* p, const uint2 v) {
    *reinterpret_cast<uint2*>(p) = v;
}
__device__ __forceinline__ u64 pk1(float s) {
    u64 r; unsigned u = __float_as_uint(s);
    asm("mov.b64 %0, {%1, %1};" : "=l"(r) : "r"(u));
    return r;
}
__device__ __forceinline__ u64 pk2(float lo, float hi) {
    u64 r;
    asm("mov.b64 %0, {%1, %2};" : "=l"(r)
        : "r"(__float_as_uint(lo)), "r"(__float_as_uint(hi)));
    return r;
}
__device__ __forceinline__ void upk(u64 v, float& lo, float& hi) {
    unsigned a, b;
    asm("mov.b64 {%0, %1}, %2;" : "=r"(a), "=r"(b) : "l"(v));
    lo = __uint_as_float(a); hi = __uint_as_float(b);
}
// bf16x2 (u32) -> f32x2 (u64): bf16 bits are the top half of f32
__device__ __forceinline__ u64 bfpair(unsigned v) {
    unsigned lo = v << 16, hi = v & 0xffff0000u;
    u64 r;
    asm("mov.b64 %0, {%1, %2};" : "=l"(r) : "r"(lo), "r"(hi));
    return r;
}
__device__ __forceinline__ float bflo(unsigned v) { return __uint_as_float(v << 16); }
__device__ __forceinline__ float bfhi(unsigned v) { return __uint_as_float(v & 0xffff0000u); }
__device__ __forceinline__ unsigned packbf(float lo, float hi) {
    unsigned r;
    asm("cvt.rn.bf16x2.f32 %0, %1, %2;" : "=r"(r) : "f"(hi), "f"(lo));
    return r;
}
#define FMA2(acc, s2, wv) \
    asm("fma.rn.f32x2 %0, %1, %2, %0;" : "+l"(acc) : "l"(s2), "l"(wv))

__device__ __forceinline__ float hsum16(float v) {
    v += __shfl_xor_sync(0xffffffffu, v, 1);
    v += __shfl_xor_sync(0xffffffffu, v, 2);
    v += __shfl_xor_sync(0xffffffffu, v, 4);
    v += __shfl_xor_sync(0xffffffffu, v, 8);
    return v;
}
__device__ __forceinline__ float hmax16(float v) {
    v = fmaxf(v, __shfl_xor_sync(0xffffffffu, v, 1));
    v = fmaxf(v, __shfl_xor_sync(0xffffffffu, v, 2));
    v = fmaxf(v, __shfl_xor_sync(0xffffffffu, v, 4));
    v = fmaxf(v, __shfl_xor_sync(0xffffffffu, v, 8));
    return v;
}

__global__ __launch_bounds__(NTHR, 1) void wda_kernel(
    const float* __restrict__ turb, const float* __restrict__ weath,
    const float* __restrict__ w_t,  const float* __restrict__ b_t,
    const float* __restrict__ w_w,  const float* __restrict__ b_w,
    const float* __restrict__ g_t,  const float* __restrict__ be_t,
    const float* __restrict__ g_w,  const float* __restrict__ be_w,
    const float* __restrict__ w_qkv,const float* __restrict__ b_qkv,
    const float* __restrict__ w_ao, const float* __restrict__ b_ao,
    const float* __restrict__ w_op, const float* __restrict__ b_op,
    float* __restrict__ out)
{
    extern __shared__ float sm[];
    u32t* smu = reinterpret_cast<u32t*>(sm);
    const int tid  = threadIdx.x;
    const int warp = tid >> 5, lane = tid & 31;
    const int hh   = lane >> 4;
    const int hh2  = hh * 2;
    const int et   = lane & 15;
    const int e4   = et * 4;
    const int et2  = et * 2;
    const size_t s = blockIdx.x;
    const float* turb_s  = turb  + s * (size_t)(NT * CM);
    const float* weath_s = weath + s * (size_t)(NW * CM);
    float*       out_s   = out   + s * (size_t)(NT * CM);

    // zero V pad rows 200..207 (stage-4 context over-reads with p=0)
    for (int i = tid; i < 8 * 34; i += NTHR) smu[VU + 200 * 34 + i] = 0u;

    // ============ Stage 1: h = LN(x @ W^T + b), full-K single pass ========
#pragma unroll 1
    for (int src = 0; src < 2; ++src) {
        const float* inp = src ? weath_s : turb_s;
        const float* Wg  = src ? w_w  : w_t;
        const float* bg  = src ? b_w  : b_t;
        const float* gg  = src ? g_w  : g_t;
        const float* beg = src ? be_w : be_t;
        const int ngrp   = src ? 13 : 25;
        const int rmax   = src ? NW - 1 : NT - 1;
        u32t* hb = smu + (src ? KU : VU);
        const float4 bv = ld4(bg + e4), gv = ld4(gg + e4), ev = ld4(beg + e4);

        __syncthreads();
        // stage full wT [256 c][34 u32]: cols packed in bf16 pairs
        for (int idx = tid; idx < 256 * 32; idx += NTHR) {
            const int c = idx & 255, j = idx >> 8;
            smu[WU + c * 34 + j] =
                packbf(Wg[(2 * j) * 256 + c], Wg[(2 * j + 1) * 256 + c]);
        }
        __syncthreads();
#pragma unroll 1
        for (int g = warp; g < ngrp; g += NWARP) {
            const int r0 = g * 8 + hh * 4;
            const float* xp0 = inp + (size_t)min(r0 + 0, rmax) * CM;
            const float* xp1 = inp + (size_t)min(r0 + 1, rmax) * CM;
            const float* xp2 = inp + (size_t)min(r0 + 2, rmax) * CM;
            const float* xp3 = inp + (size_t)min(r0 + 3, rmax) * CM;
            u64 ac[4][2] = {};
#pragma unroll 2
            for (int k = 0; k < 256; k += 4) {
                const float4 x0 = ld4(xp0 + k), x1 = ld4(xp1 + k);
                const float4 x2 = ld4(xp2 + k), x3 = ld4(xp3 + k);
                const u32t* wp = smu + WU + k * 34 + et2;
                const uint2 c0 = ld2u(wp),      c1 = ld2u(wp + 34),
                            c2 = ld2u(wp + 68), c3 = ld2u(wp + 102);
                const u64 w00 = bfpair(c0.x), w01 = bfpair(c0.y);
                const u64 w10 = bfpair(c1.x), w11 = bfpair(c1.y);
                const u64 w20 = bfpair(c2.x), w21 = bfpair(c2.y);
                const u64 w30 = bfpair(c3.x), w31 = bfpair(c3.y);
#define S1ROW(i, xv) { \
                u64 s_ = pk1((xv).x); FMA2(ac[i][0], s_, w00); FMA2(ac[i][1], s_, w01); \
                s_ = pk1((xv).y);     FMA2(ac[i][0], s_, w10); FMA2(ac[i][1], s_, w11); \
                s_ = pk1((xv).z);     FMA2(ac[i][0], s_, w20); FMA2(ac[i][1], s_, w21); \
                s_ = pk1((xv).w);     FMA2(ac[i][0], s_, w30); FMA2(ac[i][1], s_, w31); }
                S1ROW(0, x0) S1ROW(1, x1) S1ROW(2, x2) S1ROW(3, x3)
#undef S1ROW
            }
#pragma unroll
            for (int i = 0; i < 4; ++i) {
                float y0, y1, y2, y3;
                upk(ac[i][0], y0, y1); upk(ac[i][1], y2, y3);
                y0 += bv.x; y1 += bv.y; y2 += bv.z; y3 += bv.w;
                const float mu = hsum16(y0 + y1 + y2 + y3) * 0.015625f;
                const float qq = hsum16(y0*y0 + y1*y1 + y2*y2 + y3*y3) * 0.015625f;
                const float rs = rsqrtf(qq - mu * mu + 1e-5f);
                y0 = (y0 - mu) * rs * gv.x + ev.x;
                y1 = (y1 - mu) * rs * gv.y + ev.y;
                y2 = (y2 - mu) * rs * gv.z + ev.z;
                y3 = (y3 - mu) * rs * gv.w + ev.w;
                uint2 hv; hv.x = packbf(y0, y1); hv.y = packbf(y2, y3);
                st2u(hb + (r0 + i) * 34 + et2, hv);
            }
        }
    }
    __syncthreads();

    // prestage stage-3 QKV weights (W region free; ordered by stage-2-end sync)
    for (int idx = tid; idx < 64 * 96; idx += NTHR) {
        const int d = idx & 63, j = idx >> 6;
        smu[WU + d * 98 + j] =
            packbf(w_qkv[(2 * j) * 64 + d], w_qkv[(2 * j + 1) * 64 + d]);
    }

    // ============ Stage 2: cross-attention ================================
    {
        float* P  = sm + PF + warp * 832;
        float* pA = P + hh2 * 112;
        float* pB = pA + 112;
        int moff[7];
#pragma unroll
        for (int j = 0; j < 7; ++j)
            moff[j] = KU + min(et + 16 * j, NW - 1) * 34;
#pragma unroll 1
        for (int g = warp; g < NT / 4; g += NWARP) {
            const int rA = g * 4 + hh2;
            const u32t* qpa = smu + VU + rA * 34;
            const u32t* qpb = qpa + 34;
            u64 la[7] = {}, lb[7] = {};
#pragma unroll 4
            for (int dc = 0; dc < 32; dc += 2) {
                const uint2 qa = ld2u(qpa + dc), qb = ld2u(qpb + dc);
                const u64 qa0 = bfpair(qa.x), qa1 = bfpair(qa.y);
                const u64 qb0 = bfpair(qb.x), qb1 = bfpair(qb.y);
#pragma unroll
                for (int j = 0; j < 7; ++j) {
                    const uint2 kv = ld2u(smu + moff[j] + dc);
                    const u64 k0 = bfpair(kv.x), k1 = bfpair(kv.y);
                    FMA2(la[j], qa0, k0); FMA2(la[j], qa1, k1);
                    FMA2(lb[j], qb0, k0); FMA2(lb[j], qb1, k1);
                }
            }
            float lA[7], lB[7];
#pragma unroll
            for (int j = 0; j < 7; ++j) {
                float lo, hi;
                upk(la[j], lo, hi); lA[j] = lo + hi;
                upk(lb[j], lo, hi); lB[j] = lo + hi;
            }
            float mA = -1e30f, mB = -1e30f;
#pragma unroll
            for (int j = 0; j < 7; ++j) {
                const bool ok = et + 16 * j < NW;
                lA[j] = ok ? lA[j] * 0.125f : -1e30f;
                lB[j] = ok ? lB[j] * 0.125f : -1e30f;
                mA = fmaxf(mA, lA[j]); mB = fmaxf(mB, lB[j]);
            }
            mA = hmax16(mA); mB = hmax16(mB);
            float sA = 0.f, sB = 0.f;
#pragma unroll
            for (int j = 0; j < 7; ++j) {
                const bool ok = et + 16 * j < NW;
                lA[j] = ok ? __expf(lA[j] - mA) : 0.f;
                lB[j] = ok ? __expf(lB[j] - mB) : 0.f;
                sA += lA[j]; sB += lB[j];
            }
            const float iA = 1.f / hsum16(sA), iB = 1.f / hsum16(sB);
#pragma unroll
            for (int j = 0; j < 7; ++j) {
                const int m = et + 16 * j;
                if (m < NW) { pA[m] = lA[j] * iA; pB[m] = lB[j] * iB; }
            }
            __syncwarp();
            u64 c0A = 0, c1A = 0, c0B = 0, c1B = 0;
#pragma unroll 5
            for (int m = 0; m < NW; m += 4) {
                const float4 pa = ld4(pA + m), pb = ld4(pB + m);
                const u32t* kp = smu + KU + m * 34 + et2;
                const uint2 m0 = ld2u(kp),      m1 = ld2u(kp + 34),
                            m2 = ld2u(kp + 68), m3 = ld2u(kp + 102);
                const u64 w00 = bfpair(m0.x), w01 = bfpair(m0.y);
                const u64 w10 = bfpair(m1.x), w11 = bfpair(m1.y);
                const u64 w20 = bfpair(m2.x), w21 = bfpair(m2.y);
                const u64 w30 = bfpair(m3.x), w31 = bfpair(m3.y);
                u64 s_;
                s_ = pk1(pa.x); FMA2(c0A, s_, w00); FMA2(c1A, s_, w01);
                s_ = pk1(pa.y); FMA2(c0A, s_, w10); FMA2(c1A, s_, w11);
                s_ = pk1(pa.z); FMA2(c0A, s_, w20); FMA2(c1A, s_, w21);
                s_ = pk1(pa.w); FMA2(c0A, s_, w30); FMA2(c1A, s_, w31);
                s_ = pk1(pb.x); FMA2(c0B, s_, w00); FMA2(c1B, s_, w01);
                s_ = pk1(pb.y); FMA2(c0B, s_, w10); FMA2(c1B, s_, w11);
                s_ = pk1(pb.z); FMA2(c0B, s_, w20); FMA2(c1B, s_, w21);
                s_ = pk1(pb.w); FMA2(c0B, s_, w30); FMA2(c1B, s_, w31);
            }
            st4u(sm + OFF_X + rA * 64 + e4, c0A, c1A);
            st4u(sm + OFF_X + (rA + 1) * 64 + e4, c0B, c1B);
            __syncwarp();
        }
    }
    __syncthreads();

    // ============ Stage 3: QKV projection ==================================
    {
        const float4 bq0 = ld4(b_qkv + e4), bq1 = ld4(b_qkv + 64 + e4),
                     bq2 = ld4(b_qkv + 128 + e4);
#pragma unroll 1
        for (int g = warp; g < NT / 4; g += NWARP) {
            const int rA = g * 4 + hh2;
            const float* xA = sm + OFF_X + rA * 64;
            const float* xB = xA + 64;
            u64 q0A = pk2(bq0.x, bq0.y), q1A = pk2(bq0.z, bq0.w);
            u64 k0A = pk2(bq1.x, bq1.y), k1A = pk2(bq1.z, bq1.w);
            u64 v0A = pk2(bq2.x, bq2.y), v1A = pk2(bq2.z, bq2.w);
            u64 q0B = q0A, q1B = q1A, k0B = k0A, k1B = k1A, v0B = v0A, v1B = v1A;
#pragma unroll 4
            for (int d = 0; d < 64; d += 4) {
                const float4 a = ld4(xA + d), b = ld4(xB + d);
#define QKV_STEP(xa, xb, dd) { \
                const u32t* wp = smu + WU + (d + dd) * 98 + et2; \
                const uint2 uq = ld2u(wp), uk = ld2u(wp + 32), uv = ld2u(wp + 64); \
                const u64 wq0 = bfpair(uq.x), wq1 = bfpair(uq.y); \
                const u64 wk0 = bfpair(uk.x), wk1 = bfpair(uk.y); \
                const u64 wv0 = bfpair(uv.x), wv1 = bfpair(uv.y); \
                const u64 sa_ = pk1(xa), sb_ = pk1(xb); \
                FMA2(q0A, sa_, wq0); FMA2(q1A, sa_, wq1); \
                FMA2(k0A, sa_, wk0); FMA2(k1A, sa_, wk1); \
                FMA2(v0A, sa_, wv0); FMA2(v1A, sa_, wv1); \
                FMA2(q0B, sb_, wq0); FMA2(q1B, sb_, wq1); \
                FMA2(k0B, sb_, wk0); FMA2(k1B, sb_, wk1); \
                FMA2(v0B, sb_, wv0); FMA2(v1B, sb_, wv1); }
                QKV_STEP(a.x, b.x, 0) QKV_STEP(a.y, b.y, 1)
                QKV_STEP(a.z, b.z, 2) QKV_STEP(a.w, b.w, 3)
#undef QKV_STEP
            }
            st4u(sm + OFF_X + rA * 64 + e4, q0A, q1A);      // q fp32, overwrites x
            st4u(sm + OFF_X + (rA + 1) * 64 + e4, q0B, q1B);
            float t0, t1, t2, t3;
            uint2 pr;
            upk(k0A, t0, t1); upk(k1A, t2, t3);
            pr.x = packbf(t0, t1); pr.y = packbf(t2, t3);
            st2u(smu + KU + rA * 34 + et2, pr);
            upk(k0B, t0, t1); upk(k1B, t2, t3);
            pr.x = packbf(t0, t1); pr.y = packbf(t2, t3);
            st2u(smu + KU + (rA + 1) * 34 + et2, pr);
            upk(v0A, t0, t1); upk(v1A, t2, t3);
            pr.x = packbf(t0, t1); pr.y = packbf(t2, t3);
            st2u(smu + VU + rA * 34 + et2, pr);
            upk(v0B, t0, t1); upk(v1B, t2, t3);
            pr.x = packbf(t0, t1); pr.y = packbf(t2, t3);
            st2u(smu + VU + (rA + 1) * 34 + et2, pr);
        }
    }
    __syncthreads();

    // prestage stage-5 weights (W free; stage 4 doesn't touch W)
    for (int idx = tid; idx < 64 * 32; idx += NTHR) {
        const int d = idx & 63, j = idx >> 6;
        smu[WU + d * 34 + j] =
            packbf(w_ao[(2 * j) * 64 + d], w_ao[(2 * j + 1) * 64 + d]);
    }
    for (int idx = tid; idx < 64 * 128; idx += NTHR) {
        const int e = idx & 63, j = idx >> 6;
        smu[OPU + e * 130 + j] =
            packbf(w_op[(2 * j) * 64 + e], w_op[(2 * j + 1) * 64 + e]);
    }

    // ============ Stage 4: 4-head self-attention (o overwrites q) ==========
    {
        float* P  = sm + PF + warp * 832;          // [4][208]
        float* pA = P + hh2 * 208;
        float* pB = pA + 208;
        const int ms = et >> 2, dd4 = (et & 3) * 4;
        int koff[13];
#pragma unroll
        for (int j = 0; j < 13; ++j)
            koff[j] = KU + min(et + 16 * j, NT - 1) * 34;
#pragma unroll 1
        for (int g = warp; g < NT / 4; g += NWARP) {
            const int rA = g * 4 + hh2;
            if (et < 8) { pA[200 + et] = 0.f; pB[200 + et] = 0.f; }
#pragma unroll 1
            for (int hd0 = 0; hd0 < 64; hd0 += 16) {
                const int hc = hd0 >> 1;
                const float* qA = sm + OFF_X + rA * 64 + hd0;
                const float* qB = qA + 64;
                float lA[13], lB[13];
#pragma unroll
                for (int j = 0; j < 13; ++j) { lA[j] = 0.f; lB[j] = 0.f; }
#pragma unroll
                for (int d = 0; d < 16; d += 4) {
                    const float4 a = ld4(qA + d), b = ld4(qB + d);
#pragma unroll
                    for (int j = 0; j < 13; ++j) {
                        const uint2 kv = ld2u(smu + koff[j] + hc + (d >> 1));
                        const float k0 = bflo(kv.x), k1 = bfhi(kv.x);
                        const float k2 = bflo(kv.y), k3 = bfhi(kv.y);
                        lA[j] = fmaf(a.w, k3, fmaf(a.z, k2,
                                fmaf(a.y, k1, fmaf(a.x, k0, lA[j]))));
                        lB[j] = fmaf(b.w, k3, fmaf(b.z, k2,
                                fmaf(b.y, k1, fmaf(b.x, k0, lB[j]))));
                    }
                }
                float mA = -1e30f, mB = -1e30f;
#pragma unroll
                for (int j = 0; j < 13; ++j) {
                    const bool ok = et + 16 * j < NT;
                    lA[j] = ok ? lA[j] * 0.25f : -1e30f;
                    lB[j] = ok ? lB[j] * 0.25f : -1e30f;
                    mA = fmaxf(mA, lA[j]); mB = fmaxf(mB, lB[j]);
                }
                mA = hmax16(mA); mB = hmax16(mB);
                float sA = 0.f, sB = 0.f;
#pragma unroll
                for (int j = 0; j < 13; ++j) {
                    const bool ok = et + 16 * j < NT;
                    lA[j] = ok ? __expf(lA[j] - mA) : 0.f;
                    lB[j] = ok ? __expf(lB[j] - mB) : 0.f;
                    sA += lA[j]; sB += lB[j];
                }
                const float iA = 1.f / hsum16(sA), iB = 1.f / hsum16(sB);
#pragma unroll
                for (int j = 0; j < 13; ++j) {
                    const int m = et + 16 * j;
                    if (m < NT) { pA[m] = lA[j] * iA; pB[m] = lB[j] * iB; }
                }
                __syncwarp();
                u64 o0A = 0, o1A = 0, o0B = 0, o1B = 0;
                const int m0 = ms * 52;
                const int vcol = hc + (et & 3) * 2;
#pragma unroll
                for (int mi = 0; mi < 52; mi += 4) {
                    const int m = m0 + mi;
                    const float4 pa = ld4(pA + m), pb = ld4(pB + m);
                    const u32t* vp = smu + VU + m * 34 + vcol;
                    const uint2 r0 = ld2u(vp),      r1 = ld2u(vp + 34),
                                r2 = ld2u(vp + 68), r3 = ld2u(vp + 102);
                    const u64 v00 = bfpair(r0.x), v01 = bfpair(r0.y);
                    const u64 v10 = bfpair(r1.x), v11 = bfpair(r1.y);
                    const u64 v20 = bfpair(r2.x), v21 = bfpair(r2.y);
                    const u64 v30 = bfpair(r3.x), v31 = bfpair(r3.y);
                    u64 s_;
                    s_ = pk1(pa.x); FMA2(o0A, s_, v00); FMA2(o1A, s_, v01);
                    s_ = pk1(pa.y); FMA2(o0A, s_, v10); FMA2(o1A, s_, v11);
                    s_ = pk1(pa.z); FMA2(o0A, s_, v20); FMA2(o1A, s_, v21);
                    s_ = pk1(pa.w); FMA2(o0A, s_, v30); FMA2(o1A, s_, v31);
                    s_ = pk1(pb.x); FMA2(o0B, s_, v00); FMA2(o1B, s_, v01);
                    s_ = pk1(pb.y); FMA2(o0B, s_, v10); FMA2(o1B, s_, v11);
                    s_ = pk1(pb.z); FMA2(o0B, s_, v20); FMA2(o1B, s_, v21);
                    s_ = pk1(pb.w); FMA2(o0B, s_, v30); FMA2(o1B, s_, v31);
                }
                float4 oA, oB;
                upk(o0A, oA.x, oA.y); upk(o1A, oA.z, oA.w);
                upk(o0B, oB.x, oB.y); upk(o1B, oB.z, oB.w);
#define RED48(c) { c += __shfl_xor_sync(0xffffffffu, c, 4); \
                   c += __shfl_xor_sync(0xffffffffu, c, 8); }
                RED48(oA.x) RED48(oA.y) RED48(oA.z) RED48(oA.w)
                RED48(oB.x) RED48(oB.y) RED48(oB.z) RED48(oB.w)
#undef RED48
                if (ms == 0) {
                    st4(sm + OFF_X + rA * 64 + hd0 + dd4, oA);
                    st4(sm + OFF_X + (rA + 1) * 64 + hd0 + dd4, oB);
                }
                __syncwarp();
            }
        }
    }
    __syncthreads();

    // ============ Stage 5: attn_out -> out_proj + residual =================
    {
        const float4 bao  = ld4(b_ao + e4);
        const float4 bop0 = ld4(b_op + e4),       bop1 = ld4(b_op + 64 + e4),
                     bop2 = ld4(b_op + 128 + e4), bop3 = ld4(b_op + 192 + e4);
        float* Abuf = sm + PF + warp * 832;       // probs region, dead now
#pragma unroll 1
        for (int g = warp; g < NT / 4; g += NWARP) {
            const int rA = g * 4 + hh2;
            const float* oA = sm + OFF_X + rA * 64;
            const float* oB = oA + 64;
            u64 a0A = pk2(bao.x, bao.y), a1A = pk2(bao.z, bao.w);
            u64 a0B = a0A, a1B = a1A;
#pragma unroll 4
            for (int d = 0; d < 64; d += 4) {
                const float4 a = ld4(oA + d), b = ld4(oB + d);
                const u32t* wp = smu + WU + d * 34 + et2;
                const uint2 c0 = ld2u(wp),      c1 = ld2u(wp + 34),
                            c2 = ld2u(wp + 68), c3 = ld2u(wp + 102);
                const u64 w00 = bfpair(c0.x), w01 = bfpair(c0.y);
                const u64 w10 = bfpair(c1.x), w11 = bfpair(c1.y);
                const u64 w20 = bfpair(c2.x), w21 = bfpair(c2.y);
                const u64 w30 = bfpair(c3.x), w31 = bfpair(c3.y);
                u64 s_;
                s_ = pk1(a.x); FMA2(a0A, s_, w00); FMA2(a1A, s_, w01);
                s_ = pk1(a.y); FMA2(a0A, s_, w10); FMA2(a1A, s_, w11);
                s_ = pk1(a.z); FMA2(a0A, s_, w20); FMA2(a1A, s_, w21);
                s_ = pk1(a.w); FMA2(a0A, s_, w30); FMA2(a1A, s_, w31);
                s_ = pk1(b.x); FMA2(a0B, s_, w00); FMA2(a1B, s_, w01);
                s_ = pk1(b.y); FMA2(a0B, s_, w10); FMA2(a1B, s_, w11);
                s_ = pk1(b.z); FMA2(a0B, s_, w20); FMA2(a1B, s_, w21);
                s_ = pk1(b.w); FMA2(a0B, s_, w30); FMA2(a1B, s_, w31);
            }
            st4u(Abuf + hh2 * 68 + e4, a0A, a1A);
            st4u(Abuf + hh2 * 68 + 68 + e4, a0B, a1B);
            __syncwarp();
            const float* tA = turb_s + (size_t)rA * CM;
            const float* tB = tA + CM;
            float* outA = out_s + (size_t)rA * CM;
            float* outB = outA + CM;
            u64 aA[8], aB[8];
            {
                float4 r;
                r = ld4(tA + e4);
                aA[0] = pk2(bop0.x + r.x, bop0.y + r.y); aA[1] = pk2(bop0.z + r.z, bop0.w + r.w);
                r = ld4(tA + 64 + e4);
                aA[2] = pk2(bop1.x + r.x, bop1.y + r.y); aA[3] = pk2(bop1.z + r.z, bop1.w + r.w);
                r = ld4(tA + 128 + e4);
                aA[4] = pk2(bop2.x + r.x, bop2.y + r.y); aA[5] = pk2(bop2.z + r.z, bop2.w + r.w);
                r = ld4(tA + 192 + e4);
                aA[6] = pk2(bop3.x + r.x, bop3.y + r.y); aA[7] = pk2(bop3.z + r.z, bop3.w + r.w);
                r = ld4(tB + e4);
                aB[0] = pk2(bop0.x + r.x, bop0.y + r.y); aB[1] = pk2(bop0.z + r.z, bop0.w + r.w);
                r = ld4(tB + 64 + e4);
                aB[2] = pk2(bop1.x + r.x, bop1.y + r.y); aB[3] = pk2(bop1.z + r.z, bop1.w + r.w);
                r = ld4(tB + 128 + e4);
                aB[4] = pk2(bop2.x + r.x, bop2.y + r.y); aB[5] = pk2(bop2.z + r.z, bop2.w + r.w);
                r = ld4(tB + 192 + e4);
                aB[6] = pk2(bop3.x + r.x, bop3.y + r.y); aB[7] = pk2(bop3.z + r.z, bop3.w + r.w);
            }
            const float* arowA = Abuf + hh2 * 68;
            const float* arowB = arowA + 68;
#pragma unroll 2
            for (int e = 0; e < 64; e += 4) {
                const float4 a = ld4(arowA + e), b = ld4(arowB + e);
#define OP_STEP(xa, xb, ee) { \
                const u32t* wp = smu + OPU + (e + ee) * 130 + et2; \
                const uint2 u0 = ld2u(wp),      u1 = ld2u(wp + 32), \
                            u2 = ld2u(wp + 64), u3 = ld2u(wp + 96); \
                const u64 w00 = bfpair(u0.x), w01 = bfpair(u0.y); \
                const u64 w10 = bfpair(u1.x), w11 = bfpair(u1.y); \
                const u64 w20 = bfpair(u2.x), w21 = bfpair(u2.y); \
                const u64 w30 = bfpair(u3.x), w31 = bfpair(u3.y); \
                const u64 sa_ = pk1(xa), sb_ = pk1(xb); \
                FMA2(aA[0], sa_, w00); FMA2(aA[1], sa_, w01); \
                FMA2(aA[2], sa_, w10); FMA2(aA[3], sa_, w11); \
                FMA2(aA[4], sa_, w20); FMA2(aA[5], sa_, w21); \
                FMA2(aA[6], sa_, w30); FMA2(aA[7], sa_, w31); \
                FMA2(aB[0], sb_, w00); FMA2(aB[1], sb_, w01); \
                FMA2(aB[2], sb_, w10); FMA2(aB[3], sb_, w11); \
                FMA2(aB[4], sb_, w20); FMA2(aB[5], sb_, w21); \
                FMA2(aB[6], sb_, w30); FMA2(aB[7], sb_, w31); }
                OP_STEP(a.x, b.x, 0) OP_STEP(a.y, b.y, 1)
                OP_STEP(a.z, b.z, 2) OP_STEP(a.w, b.w, 3)
#undef OP_STEP
            }
            st4u(outA + e4,       aA[0], aA[1]); st4u(outA + 64 + e4,  aA[2], aA[3]);
            st4u(outA + 128 + e4, aA[4], aA[5]); st4u(outA + 192 + e4, aA[6], aA[7]);
            st4u(outB + e4,       aB[0], aB[1]); st4u(outB + 64 + e4,  aB[2], aB[3]);
            st4u(outB + 128 + e4, aB[4], aB[5]); st4u(outB + 192 + e4, aB[6], aB[7]);
            __syncwarp();
        }
    }
}

extern "C" void kernel_launch(void* const* d_in, const int* in_sizes, int n_in,
                              void* d_out, int out_size)
{
    const float* turb  = (const float*)d_in[0];
    const float* weath = (const float*)d_in[1];
    const float* w_t   = (const float*)d_in[2];
    const float* b_t   = (const float*)d_in[3];
    const float* w_w   = (const float*)d_in[4];
    const float* b_w   = (const float*)d_in[5];
    const float* g_t   = (const float*)d_in[6];
    const float* be_t  = (const float*)d_in[7];
    const float* g_w   = (const float*)d_in[8];
    const float* be_w  = (const float*)d_in[9];
    const float* w_qkv = (const float*)d_in[10];
    const float* b_qkv = (const float*)d_in[11];
    const float* w_ao  = (const float*)d_in[12];
    const float* b_ao  = (const float*)d_in[13];
    const float* w_op  = (const float*)d_in[14];
    const float* b_op  = (const float*)d_in[15];
    float* out = (float*)d_out;

    const int S = in_sizes[0] / (NT * CM);   // 768
    const size_t smem = (size_t)SMEM_F * sizeof(float);
    cudaFuncSetAttribute(wda_kernel, cudaFuncAttributeMaxDynamicSharedMemorySize,
                         (int)smem);
    wda_kernel<<<S, NTHR, smem>>>(turb, weath, w_t, b_t, w_w, b_w,
                                  g_t, be_t, g_w, be_w, w_qkv, b_qkv,
                                  w_ao, b_ao, w_op, b_op, out);
}